// round 16
// baseline (speedup 1.0000x reference)
#include <cuda_runtime.h>
#include <cstdint>
#include <cstddef>

#define Tn 1024
#define Bn 512
#define Hn 128
#define In 64
#define G3 384
#define NTILES 8192          // (Bn*Tn)/64 row-tiles
#define GSTRIDE 74           // persistent grid x-dim (74*2*2blk/SM covers 148 SMs)

// 805 MB scratch for precomputed input-side gate projections: xg[b][t][g]
__device__ float g_xg[(size_t)Bn * Tn * G3];

// ---------------------------------------------------------------------------
// Helpers
// ---------------------------------------------------------------------------
__device__ __forceinline__ void ffma2(unsigned long long& d,
                                      const unsigned long long a,
                                      const unsigned long long b) {
    asm("fma.rn.f32x2 %0, %1, %2, %0;" : "+l"(d) : "l"(a), "l"(b));
}

__device__ __forceinline__ float hsum2(unsigned long long v) {
    float lo, hi;
    asm("mov.b64 {%0, %1}, %2;" : "=f"(lo), "=f"(hi) : "l"(v));
    return lo + hi;
}

__device__ __forceinline__ float sigf(float x) {
    return __fdividef(1.0f, 1.0f + __expf(-x));
}
__device__ __forceinline__ float tanh_fast(float x) {
    return 1.0f - __fdividef(2.0f, 1.0f + __expf(2.0f * x));
}

__device__ __forceinline__ uint32_t smem_u32(const void* p) {
    uint32_t a;
    asm("{ .reg .u64 t; cvta.to.shared.u64 t, %1; cvt.u32.u64 %0, t; }"
        : "=r"(a) : "l"(p));
    return a;
}
#define CP_ASYNC16(dst_u32, src_ptr) \
    asm volatile("cp.async.cg.shared.global [%0], [%1], 16;" \
                 :: "r"(dst_u32), "l"(src_ptr))
#define CP_COMMIT() asm volatile("cp.async.commit_group;")
#define CP_WAIT1()  asm volatile("cp.async.wait_group 1;" ::: "memory")

// ---------------------------------------------------------------------------
// Kernel 1 (persistent, 3-buffer pipeline, ONE sync per tile):
// xg[r][g] = x[r][:] . W_ih[g][:] + b_ih[g] + (g<256 ? b_hh[g] : 0)
// Grid 74 x 4 = 296 blocks (2/SM). Block keeps its 96-gate W tile in smem
// for its whole life; loops over ~111 64-row X tiles through a rotating
// 3-buffer cp.async pipeline. Inner compute = proven 4x6 FFMA2 thread tile.
// ---------------------------------------------------------------------------
// dynamic smem layout (floats)
#define GX_WS   0                       // [96][68]  = 6528
#define GX_XS   (96 * 68)               // [3][64*64] = 12288
#define GX_FLOATS (GX_XS + 3 * 64 * 64)
#define GX_BYTES  (GX_FLOATS * 4)

__global__ void __launch_bounds__(256, 2)
xg_gemm(const float* __restrict__ x,
        const float* __restrict__ Wih,
        const float* __restrict__ bih,
        const float* __restrict__ bhh) {
    extern __shared__ __align__(16) float smg[];
    float* ws = smg + GX_WS;            // [96][68] padded

    const int tid = threadIdx.x;
    const int cb = blockIdx.y;          // 0..3 -> 96 gate-cols

    // One-time W tile load
    {
        const float4* wg4 = (const float4*)(Wih + (size_t)cb * 96 * 64);
        #pragma unroll
        for (int i = tid; i < 96 * 16; i += 256) {
            int g = i >> 4, k4 = i & 15;
            *(float4*)(ws + g * 68 + k4 * 4) = wg4[i];
        }
    }

    const int ry = tid >> 4;   // 0..15 -> rows ry*4 .. +4
    const int cx = tid & 15;   // cols cx + 16*jj

    // Per-thread bias for its 6 gate columns
    float bias[6];
    #pragma unroll
    for (int jj = 0; jj < 6; jj++) {
        const int g = cb * 96 + cx + 16 * jj;
        bias[jj] = bih[g] + (g < 256 ? bhh[g] : 0.0f);
    }

    // Rotating 3-buffer pipeline state (scalar rotation, no dynamic index)
    float* cur = smg + GX_XS;
    float* nxt = cur + 64 * 64;
    float* fre = nxt + 64 * 64;
    uint32_t cur_a = smem_u32(cur);
    uint32_t nxt_a = smem_u32(nxt);
    uint32_t fre_a = smem_u32(fre);

    // Prologue: prefetch tile0 -> cur, tile1 -> nxt
    {
        const float4* s0 = (const float4*)(x + (size_t)blockIdx.x * 64 * 64);
        #pragma unroll
        for (int i = 0; i < 4; i++) {
            int e = tid + i * 256;
            CP_ASYNC16(cur_a + e * 16, s0 + e);
        }
        CP_COMMIT();
        const int t1 = blockIdx.x + GSTRIDE;
        if (t1 < NTILES) {
            const float4* s1 = (const float4*)(x + (size_t)t1 * 64 * 64);
            #pragma unroll
            for (int i = 0; i < 4; i++) {
                int e = tid + i * 256;
                CP_ASYNC16(nxt_a + e * 16, s1 + e);
            }
        }
        CP_COMMIT();
    }

    for (int tile = blockIdx.x; tile < NTILES; tile += GSTRIDE) {
        CP_WAIT1();          // cur's group complete (<=1 group pending)
        __syncthreads();     // cur visible to all; prior readers of fre done

        // Prefetch tile+2 into fre (overlaps compute+store below)
        const int t2 = tile + 2 * GSTRIDE;
        if (t2 < NTILES) {
            const float4* s2 = (const float4*)(x + (size_t)t2 * 64 * 64);
            #pragma unroll
            for (int i = 0; i < 4; i++) {
                int e = tid + i * 256;
                CP_ASYNC16(fre_a + e * 16, s2 + e);
            }
        }
        CP_COMMIT();

        const float* xs = cur;
        unsigned long long acc[4][6];
        #pragma unroll
        for (int i = 0; i < 4; i++)
            #pragma unroll
            for (int jj = 0; jj < 6; jj++) acc[i][jj] = 0ULL;

        #pragma unroll
        for (int k4 = 0; k4 < 16; k4++) {
            ulonglong2 wv[6];
            #pragma unroll
            for (int jj = 0; jj < 6; jj++)
                wv[jj] = *(const ulonglong2*)(ws + (cx + 16 * jj) * 68 + k4 * 4);
            #pragma unroll
            for (int i = 0; i < 4; i++) {
                ulonglong2 xv = *(const ulonglong2*)(xs + (ry * 4 + i) * 64 + k4 * 4);
                #pragma unroll
                for (int jj = 0; jj < 6; jj++) {
                    ffma2(acc[i][jj], xv.x, wv[jj].x);
                    ffma2(acc[i][jj], xv.y, wv[jj].y);
                }
            }
        }

        const int r0 = tile * 64;
        #pragma unroll
        for (int jj = 0; jj < 6; jj++) {
            const int g = cb * 96 + cx + 16 * jj;
            #pragma unroll
            for (int i = 0; i < 4; i++) {
                const int r = r0 + ry * 4 + i;
                g_xg[(size_t)r * G3 + g] = hsum2(acc[i][jj]) + bias[jj];
            }
        }

        // Rotate buffers: cur <- nxt <- fre <- (old cur)
        float* t = cur;  uint32_t ta = cur_a;
        cur = nxt;  cur_a = nxt_a;
        nxt = fre;  nxt_a = fre_a;
        fre = t;    fre_a = ta;
    }
}

// ---------------------------------------------------------------------------
// Kernel 2: GRU recurrence + final FC. (R12 config — proven 1492 us.)
// 128 blocks x 4 batches, 256 threads, 1 block/SM. Thread: j=tid>>1,
// half=tid&1. r,z gate W row-halves in REGISTERS (128 regs); n gate
// row-half in per-thread-packed smem [tid][68]. h double-buffered;
// 1 barrier/step; cross-half reduction via shfl_xor(.,1).
// ---------------------------------------------------------------------------
#define HROW 136
__device__ __forceinline__ int hpos(int k) { return k + ((k >> 6) << 2); }

// dynamic smem (floats)
#define SM_WN    0                      // [256][68] = 17408 floats
#define SM_HS    (256 * 68)             // [2][4][HROW] = 1088 floats
#define G_SM_FLOATS (SM_HS + 2 * 4 * HROW)
#define G_SM_BYTES  (G_SM_FLOATS * 4)

__global__ void __launch_bounds__(256, 1)
gru_kernel(const float* __restrict__ Whh,
           const float* __restrict__ bhh,
           const float* __restrict__ Wfc,
           const float* __restrict__ bfc,
           float* __restrict__ out) {
    extern __shared__ __align__(16) float sm[];
    float* wn_s = sm + SM_WN;
    float* hs = sm + SM_HS;

    const int tid = threadIdx.x;
    const int j = tid >> 1;
    const int half = tid & 1;
    const int b0 = blockIdx.x * 4;

    // n-gate W_hh row-half -> per-thread packed smem [tid][68]
    {
        const float4* src = (const float4*)(Whh + (size_t)(256 + j) * 128 + half * 64);
        #pragma unroll
        for (int kk = 0; kk < 16; kk++)
            *(float4*)(wn_s + tid * 68 + kk * 4) = src[kk];
    }
    for (int i = tid; i < 4 * HROW; i += 256) hs[i] = 0.0f;

    // r,z gate W row-halves -> registers (2 x 16 ull2 = 128 regs)
    ulonglong2 wrr[16], wzr[16];
    {
        const ulonglong2* wr_g = (const ulonglong2*)(Whh + (size_t)j * 128 + half * 64);
        const ulonglong2* wz_g = (const ulonglong2*)(Whh + (size_t)(j + 128) * 128 + half * 64);
        #pragma unroll
        for (int kk = 0; kk < 16; kk++) {
            wrr[kk] = wr_g[kk];
            wzr[kk] = wz_g[kk];
        }
    }
    const float bn = bhh[256 + j];
    float hold[2] = {0.f, 0.f};

    const size_t xgA = ((size_t)(b0 + 2 * half) * Tn) * G3 + j;
    const size_t xgB = ((size_t)(b0 + 2 * half + 1) * Tn) * G3 + j;
    const ulonglong2* wnp = (const ulonglong2*)(wn_s + tid * 68);

    __syncthreads();

    for (int t = 0; t < Tn; t++) {
        const float* hrd = hs + (t & 1) * (4 * HROW);
        float* hwr = hs + ((t & 1) ^ 1) * (4 * HROW);

        const float* xpA = g_xg + xgA + (size_t)t * G3;
        const float* xpB = g_xg + xgB + (size_t)t * G3;
        float xr0 = xpA[0], xz0 = xpA[128], xn0 = xpA[256];
        float xr1 = xpB[0], xz1 = xpB[128], xn1 = xpB[256];

        unsigned long long acc[3][4];
        #pragma unroll
        for (int g = 0; g < 3; g++)
            #pragma unroll
            for (int b = 0; b < 4; b++) acc[g][b] = 0ULL;

        const float* hbase = hrd + half * 68;
        #pragma unroll
        for (int kk = 0; kk < 16; kk++) {
            const ulonglong2 wr = wrr[kk], wz = wzr[kk];
            const ulonglong2 wn = wnp[kk];
            #pragma unroll
            for (int b = 0; b < 4; b++) {
                ulonglong2 hv = *(const ulonglong2*)(hbase + b * HROW + kk * 4);
                ffma2(acc[0][b], wr.x, hv.x); ffma2(acc[0][b], wr.y, hv.y);
                ffma2(acc[1][b], wz.x, hv.x); ffma2(acc[1][b], wz.y, hv.y);
                ffma2(acc[2][b], wn.x, hv.x); ffma2(acc[2][b], wn.y, hv.y);
            }
        }

        float s[3][4];
        #pragma unroll
        for (int g = 0; g < 3; g++)
            #pragma unroll
            for (int b = 0; b < 4; b++) s[g][b] = hsum2(acc[g][b]);

        float tot[3][2];
        #pragma unroll
        for (int g = 0; g < 3; g++) {
            #pragma unroll
            for (int i = 0; i < 2; i++) {
                float keepv = half ? s[g][2 + i] : s[g][i];
                float sendv = half ? s[g][i] : s[g][2 + i];
                tot[g][i] = keepv + __shfl_xor_sync(0xFFFFFFFFu, sendv, 1);
            }
        }

        {
            float r0g = sigf(xr0 + tot[0][0]);
            float z0g = sigf(xz0 + tot[1][0]);
            float n0g = tanh_fast(fmaf(r0g, tot[2][0] + bn, xn0));
            float h0n = fmaf(z0g, hold[0] - n0g, n0g);
            hold[0] = h0n;
            hwr[(2 * half + 0) * HROW + hpos(j)] = h0n;

            float r1g = sigf(xr1 + tot[0][1]);
            float z1g = sigf(xz1 + tot[1][1]);
            float n1g = tanh_fast(fmaf(r1g, tot[2][1] + bn, xn1));
            float h1n = fmaf(z1g, hold[1] - n1g, n1g);
            hold[1] = h1n;
            hwr[(2 * half + 1) * HROW + hpos(j)] = h1n;
        }

        __syncthreads();
    }

    // Final h is in buffer 0. FC: out[b][o] = h_T[b] . W_fc[o] + b_fc[o]
    if (tid < 4 * 51) {
        const int b = tid / 51, o = tid % 51;
        float a = bfc[o];
        const float* wf = Wfc + o * 128;
        const float* hp = hs + b * HROW;
        #pragma unroll 8
        for (int k = 0; k < 128; k++) a = fmaf(hp[hpos(k)], wf[k], a);
        out[(b0 + b) * 51 + o] = a;
    }
}

// ---------------------------------------------------------------------------
// Launch
// ---------------------------------------------------------------------------
extern "C" void kernel_launch(void* const* d_in, const int* in_sizes, int n_in,
                              void* d_out, int out_size) {
    const float* x    = (const float*)d_in[0];  // [512,1,1024,64]
    const float* Wih  = (const float*)d_in[1];  // [384,64]
    const float* Whh  = (const float*)d_in[2];  // [384,128]
    const float* bih  = (const float*)d_in[3];  // [384]
    const float* bhh  = (const float*)d_in[4];  // [384]
    const float* Wfc  = (const float*)d_in[5];  // [51,128]
    const float* bfc  = (const float*)d_in[6];  // [51]
    float* out = (float*)d_out;                 // [512,51]

    static int attr_done = 0;
    if (!attr_done) {
        cudaFuncSetAttribute(xg_gemm,
                             cudaFuncAttributeMaxDynamicSharedMemorySize,
                             GX_BYTES);
        cudaFuncSetAttribute(gru_kernel,
                             cudaFuncAttributeMaxDynamicSharedMemorySize,
                             G_SM_BYTES);
        attr_done = 1;
    }

    xg_gemm<<<dim3(GSTRIDE, 4, 1), 256, GX_BYTES>>>(x, Wih, bih, bhh);
    gru_kernel<<<128, 256, G_SM_BYTES>>>(Whh, bhh, Wfc, bfc, out);
}

// round 17
// speedup vs baseline: 1.0164x; 1.0164x over previous
#include <cuda_runtime.h>
#include <cstdint>
#include <cstddef>

#define Tn 1024
#define Bn 512
#define Hn 128
#define In 64
#define G3 384
#define NTILES 8192          // (Bn*Tn)/64 row-tiles
#define GSTRIDE 74           // persistent grid x-dim (74 x 4 = 296 blocks = 2/SM)

// 805 MB scratch for precomputed input-side gate projections: xg[b][t][g]
__device__ float g_xg[(size_t)Bn * Tn * G3];

// ---------------------------------------------------------------------------
// Helpers
// ---------------------------------------------------------------------------
__device__ __forceinline__ void ffma2(unsigned long long& d,
                                      const unsigned long long a,
                                      const unsigned long long b) {
    asm("fma.rn.f32x2 %0, %1, %2, %0;" : "+l"(d) : "l"(a), "l"(b));
}

__device__ __forceinline__ float hsum2(unsigned long long v) {
    float lo, hi;
    asm("mov.b64 {%0, %1}, %2;" : "=f"(lo), "=f"(hi) : "l"(v));
    return lo + hi;
}

__device__ __forceinline__ float sigf(float x) {
    return __fdividef(1.0f, 1.0f + __expf(-x));
}
__device__ __forceinline__ float tanh_fast(float x) {
    return 1.0f - __fdividef(2.0f, 1.0f + __expf(2.0f * x));
}

__device__ __forceinline__ uint32_t smem_u32(const void* p) {
    uint32_t a;
    asm("{ .reg .u64 t; cvta.to.shared.u64 t, %1; cvt.u32.u64 %0, t; }"
        : "=r"(a) : "l"(p));
    return a;
}
#define CP_ASYNC16(dst_u32, src_ptr) \
    asm volatile("cp.async.cg.shared.global [%0], [%1], 16;" \
                 :: "r"(dst_u32), "l"(src_ptr))
#define CP_COMMIT() asm volatile("cp.async.commit_group;")
#define CP_WAIT1()  asm volatile("cp.async.wait_group 1;" ::: "memory")

// ---------------------------------------------------------------------------
// Kernel 1 (persistent, PER-WARP pipelines, zero block barriers in loop):
// xg[r][g] = x[r][:] . W_ih[g][:] + b_ih[g] + (g<256 ? b_hh[g] : 0)
// Grid 74 x 4 = 296 blocks (2/SM). Block keeps its 96-gate W tile in smem.
// Each warp owns rows [w*8, w*8+8) of each 64-row tile with a private
// double-buffered cp.async pipeline; warps never rendezvous after the
// W-tile prologue. Inner compute = proven 4-row x 6-col FFMA2 thread tile.
// ---------------------------------------------------------------------------
// dynamic smem layout (floats)
#define GX_WS   0                       // [96][68]  = 6528
#define GX_XS   (96 * 68)               // [8 warps][2][8*64] = 8192
#define GX_FLOATS (GX_XS + 8 * 2 * 8 * 64)
#define GX_BYTES  (GX_FLOATS * 4)

__global__ void __launch_bounds__(256, 2)
xg_gemm(const float* __restrict__ x,
        const float* __restrict__ Wih,
        const float* __restrict__ bih,
        const float* __restrict__ bhh) {
    extern __shared__ __align__(16) float smg[];
    float* ws = smg + GX_WS;            // [96][68] padded

    const int tid = threadIdx.x;
    const int w = tid >> 5;             // warp 0..7
    const int l = tid & 31;
    const int cb = blockIdx.y;          // 0..3 -> 96 gate-cols

    // One-time W tile load (only block-wide sync in the kernel)
    {
        const float4* wg4 = (const float4*)(Wih + (size_t)cb * 96 * 64);
        #pragma unroll
        for (int i = tid; i < 96 * 16; i += 256) {
            int g = i >> 4, k4 = i & 15;
            *(float4*)(ws + g * 68 + k4 * 4) = wg4[i];
        }
    }

    const int ry = l >> 4;     // 0..1 -> local rows ry*4 .. +4 (of warp's 8)
    const int cx = l & 15;     // cols cx + 16*jj

    // Per-thread bias for its 6 gate columns
    float bias[6];
    #pragma unroll
    for (int jj = 0; jj < 6; jj++) {
        const int g = cb * 96 + cx + 16 * jj;
        bias[jj] = bih[g] + (g < 256 ? bhh[g] : 0.0f);
    }

    // Per-warp double buffer: 8 rows x 64 floats = 2 KB each
    float* xb0 = smg + GX_XS + w * 2 * 512;
    float* xb1 = xb0 + 512;
    const uint32_t xb0a = smem_u32(xb0);
    const uint32_t xb1a = smem_u32(xb1);

    __syncthreads();   // W tile visible

    // Prologue: warp prefetches its slice of tile0 into buffer 0.
    // Warp slice = rows [tile*64 + w*8, +8) = 2 KB = 128 x 16B chunks,
    // 4 chunks per lane (e = l + i*32).
    {
        const float4* s0 = (const float4*)(x + ((size_t)blockIdx.x * 64 + w * 8) * 64);
        #pragma unroll
        for (int i = 0; i < 4; i++) {
            int e = l + i * 32;
            CP_ASYNC16(xb0a + e * 16, s0 + e);
        }
    }
    CP_COMMIT();

    int buf = 0;
    for (int tile = blockIdx.x; tile < NTILES; tile += GSTRIDE) {
        // Prefetch warp's slice of tile+GS into the other buffer
        const int nt = tile + GSTRIDE;
        if (nt < NTILES) {
            const uint32_t dsta = buf ? xb0a : xb1a;
            const float4* sn = (const float4*)(x + ((size_t)nt * 64 + w * 8) * 64);
            #pragma unroll
            for (int i = 0; i < 4; i++) {
                int e = l + i * 32;
                CP_ASYNC16(dsta + e * 16, sn + e);
            }
        }
        CP_COMMIT();
        CP_WAIT1();        // current buffer's group complete; next in flight
        __syncwarp();

        const float* xs = buf ? xb1 : xb0;

        unsigned long long acc[4][6];
        #pragma unroll
        for (int i = 0; i < 4; i++)
            #pragma unroll
            for (int jj = 0; jj < 6; jj++) acc[i][jj] = 0ULL;

        #pragma unroll
        for (int k4 = 0; k4 < 16; k4++) {
            ulonglong2 wv[6];
            #pragma unroll
            for (int jj = 0; jj < 6; jj++)
                wv[jj] = *(const ulonglong2*)(ws + (cx + 16 * jj) * 68 + k4 * 4);
            #pragma unroll
            for (int i = 0; i < 4; i++) {
                ulonglong2 xv = *(const ulonglong2*)(xs + (ry * 4 + i) * 64 + k4 * 4);
                #pragma unroll
                for (int jj = 0; jj < 6; jj++) {
                    ffma2(acc[i][jj], xv.x, wv[jj].x);
                    ffma2(acc[i][jj], xv.y, wv[jj].y);
                }
            }
        }

        const int r0 = tile * 64 + w * 8;
        #pragma unroll
        for (int jj = 0; jj < 6; jj++) {
            const int g = cb * 96 + cx + 16 * jj;
            #pragma unroll
            for (int i = 0; i < 4; i++) {
                const int r = r0 + ry * 4 + i;
                g_xg[(size_t)r * G3 + g] = hsum2(acc[i][jj]) + bias[jj];
            }
        }

        __syncwarp();      // all lanes done reading xs before it is refilled
        buf ^= 1;
    }
}

// ---------------------------------------------------------------------------
// Kernel 2: GRU recurrence + final FC. (R12 config — proven ~1495 us.)
// 128 blocks x 4 batches, 256 threads, 1 block/SM. Thread: j=tid>>1,
// half=tid&1. r,z gate W row-halves in REGISTERS (128 regs); n gate
// row-half in per-thread-packed smem [tid][68]. h double-buffered;
// 1 barrier/step; cross-half reduction via shfl_xor(.,1).
// ---------------------------------------------------------------------------
#define HROW 136
__device__ __forceinline__ int hpos(int k) { return k + ((k >> 6) << 2); }

// dynamic smem (floats)
#define SM_WN    0                      // [256][68] = 17408 floats
#define SM_HS    (256 * 68)             // [2][4][HROW] = 1088 floats
#define G_SM_FLOATS (SM_HS + 2 * 4 * HROW)
#define G_SM_BYTES  (G_SM_FLOATS * 4)

__global__ void __launch_bounds__(256, 1)
gru_kernel(const float* __restrict__ Whh,
           const float* __restrict__ bhh,
           const float* __restrict__ Wfc,
           const float* __restrict__ bfc,
           float* __restrict__ out) {
    extern __shared__ __align__(16) float sm[];
    float* wn_s = sm + SM_WN;
    float* hs = sm + SM_HS;

    const int tid = threadIdx.x;
    const int j = tid >> 1;
    const int half = tid & 1;
    const int b0 = blockIdx.x * 4;

    // n-gate W_hh row-half -> per-thread packed smem [tid][68]
    {
        const float4* src = (const float4*)(Whh + (size_t)(256 + j) * 128 + half * 64);
        #pragma unroll
        for (int kk = 0; kk < 16; kk++)
            *(float4*)(wn_s + tid * 68 + kk * 4) = src[kk];
    }
    for (int i = tid; i < 4 * HROW; i += 256) hs[i] = 0.0f;

    // r,z gate W row-halves -> registers (2 x 16 ull2 = 128 regs)
    ulonglong2 wrr[16], wzr[16];
    {
        const ulonglong2* wr_g = (const ulonglong2*)(Whh + (size_t)j * 128 + half * 64);
        const ulonglong2* wz_g = (const ulonglong2*)(Whh + (size_t)(j + 128) * 128 + half * 64);
        #pragma unroll
        for (int kk = 0; kk < 16; kk++) {
            wrr[kk] = wr_g[kk];
            wzr[kk] = wz_g[kk];
        }
    }
    const float bn = bhh[256 + j];
    float hold[2] = {0.f, 0.f};

    const size_t xgA = ((size_t)(b0 + 2 * half) * Tn) * G3 + j;
    const size_t xgB = ((size_t)(b0 + 2 * half + 1) * Tn) * G3 + j;
    const ulonglong2* wnp = (const ulonglong2*)(wn_s + tid * 68);

    __syncthreads();

    for (int t = 0; t < Tn; t++) {
        const float* hrd = hs + (t & 1) * (4 * HROW);
        float* hwr = hs + ((t & 1) ^ 1) * (4 * HROW);

        const float* xpA = g_xg + xgA + (size_t)t * G3;
        const float* xpB = g_xg + xgB + (size_t)t * G3;
        float xr0 = xpA[0], xz0 = xpA[128], xn0 = xpA[256];
        float xr1 = xpB[0], xz1 = xpB[128], xn1 = xpB[256];

        unsigned long long acc[3][4];
        #pragma unroll
        for (int g = 0; g < 3; g++)
            #pragma unroll
            for (int b = 0; b < 4; b++) acc[g][b] = 0ULL;

        const float* hbase = hrd + half * 68;
        #pragma unroll
        for (int kk = 0; kk < 16; kk++) {
            const ulonglong2 wr = wrr[kk], wz = wzr[kk];
            const ulonglong2 wn = wnp[kk];
            #pragma unroll
            for (int b = 0; b < 4; b++) {
                ulonglong2 hv = *(const ulonglong2*)(hbase + b * HROW + kk * 4);
                ffma2(acc[0][b], wr.x, hv.x); ffma2(acc[0][b], wr.y, hv.y);
                ffma2(acc[1][b], wz.x, hv.x); ffma2(acc[1][b], wz.y, hv.y);
                ffma2(acc[2][b], wn.x, hv.x); ffma2(acc[2][b], wn.y, hv.y);
            }
        }

        float s[3][4];
        #pragma unroll
        for (int g = 0; g < 3; g++)
            #pragma unroll
            for (int b = 0; b < 4; b++) s[g][b] = hsum2(acc[g][b]);

        float tot[3][2];
        #pragma unroll
        for (int g = 0; g < 3; g++) {
            #pragma unroll
            for (int i = 0; i < 2; i++) {
                float keepv = half ? s[g][2 + i] : s[g][i];
                float sendv = half ? s[g][i] : s[g][2 + i];
                tot[g][i] = keepv + __shfl_xor_sync(0xFFFFFFFFu, sendv, 1);
            }
        }

        {
            float r0g = sigf(xr0 + tot[0][0]);
            float z0g = sigf(xz0 + tot[1][0]);
            float n0g = tanh_fast(fmaf(r0g, tot[2][0] + bn, xn0));
            float h0n = fmaf(z0g, hold[0] - n0g, n0g);
            hold[0] = h0n;
            hwr[(2 * half + 0) * HROW + hpos(j)] = h0n;

            float r1g = sigf(xr1 + tot[0][1]);
            float z1g = sigf(xz1 + tot[1][1]);
            float n1g = tanh_fast(fmaf(r1g, tot[2][1] + bn, xn1));
            float h1n = fmaf(z1g, hold[1] - n1g, n1g);
            hold[1] = h1n;
            hwr[(2 * half + 1) * HROW + hpos(j)] = h1n;
        }

        __syncthreads();
    }

    // Final h is in buffer 0. FC: out[b][o] = h_T[b] . W_fc[o] + b_fc[o]
    if (tid < 4 * 51) {
        const int b = tid / 51, o = tid % 51;
        float a = bfc[o];
        const float* wf = Wfc + o * 128;
        const float* hp = hs + b * HROW;
        #pragma unroll 8
        for (int k = 0; k < 128; k++) a = fmaf(hp[hpos(k)], wf[k], a);
        out[(b0 + b) * 51 + o] = a;
    }
}

// ---------------------------------------------------------------------------
// Launch
// ---------------------------------------------------------------------------
extern "C" void kernel_launch(void* const* d_in, const int* in_sizes, int n_in,
                              void* d_out, int out_size) {
    const float* x    = (const float*)d_in[0];  // [512,1,1024,64]
    const float* Wih  = (const float*)d_in[1];  // [384,64]
    const float* Whh  = (const float*)d_in[2];  // [384,128]
    const float* bih  = (const float*)d_in[3];  // [384]
    const float* bhh  = (const float*)d_in[4];  // [384]
    const float* Wfc  = (const float*)d_in[5];  // [51,128]
    const float* bfc  = (const float*)d_in[6];  // [51]
    float* out = (float*)d_out;                 // [512,51]

    static int attr_done = 0;
    if (!attr_done) {
        cudaFuncSetAttribute(xg_gemm,
                             cudaFuncAttributeMaxDynamicSharedMemorySize,
                             GX_BYTES);
        cudaFuncSetAttribute(gru_kernel,
                             cudaFuncAttributeMaxDynamicSharedMemorySize,
                             G_SM_BYTES);
        attr_done = 1;
    }

    xg_gemm<<<dim3(GSTRIDE, 4, 1), 256, GX_BYTES>>>(x, Wih, bih, bhh);
    gru_kernel<<<128, 256, G_SM_BYTES>>>(Whh, bhh, Wfc, bfc, out);
}